// round 15
// baseline (speedup 1.0000x reference)
#include <cuda_runtime.h>
#include <cstdint>

// BDToGEConverter: out[b,s,p,d] = sum_k W[p,d,k] * x[b,s,k], W fixed-sparse:
//   out[.,0,0]=Σ j·x[64+j]  out[.,0,1]=Σ j·x[96+j]
//   out[.,1,0]=Σ j·x[80+j]  out[.,1,1]=Σ j·x[112+j]       (j=0..15)
//   for all p: x10→d27 x11→d28 x12→d29 x13→d30 x14→d31 x15→d32
//              x16→d25 x17→d26 x18→d33 x19→d34 ; all else 0.
//
// FINAL champion (27.14us x2, 27.10us family best): warp-per-row,
// 10x immediate-offset 128-bit .cs zero-flood per lane, __syncwarp,
// 26-lane composed special overwrite. Geometry 2048 x 512.
// This sits at the DRAM-write drain floor: 168MB mandatory output/replay
// at ~6.7TB/s effective (~84% of HBM3e spec). All alternatives measured
// worse: TMA bulk store, persistent grid, write-back, L2 evict hints,
// 256-bit stores, 2-row MLP.

static constexpr int BD_DIM   = 512;
static constexpr int ROW_OUT4 = 320;     // float4 per (b,s) row
static constexpr int THREADS  = 512;     // 16 warps = 16 rows per block

__global__ __launch_bounds__(THREADS)
void bd2ge_reg(const float* __restrict__ x, float* __restrict__ out)
{
    const unsigned FULL = 0xffffffffu;
    const int t    = threadIdx.x;
    const int warp = t >> 5;
    const int lane = t & 31;

    const long long row = (long long)blockIdx.x * 16 + warp;
    const float*    g   = x + row * (long long)BD_DIM;

    // ---- per-lane input loads (issued before the store flood)
    float a0 = 0.f, a1 = 0.f, a2 = 0.f, a3 = 0.f, vop = 0.f;
    if (lane < 16) {
        const float m = (float)lane;
        a0 = __ldg(g + 64  + lane) * m;
        a1 = __ldg(g + 80  + lane) * m;
        a2 = __ldg(g + 96  + lane) * m;
        a3 = __ldg(g + 112 + lane) * m;
    } else if (lane < 26) {
        vop = __ldg(g + 10 + (lane - 16));
    }

    // ---- flood the row with zeros: 10 immediate-offset streaming stores/lane
    float4* rowb = reinterpret_cast<float4*>(out) + row * ROW_OUT4 + lane;
    const float4 z = make_float4(0.f, 0.f, 0.f, 0.f);
    #pragma unroll
    for (int i = 0; i < 10; ++i)
        __stcs(rowb + i * 32, z);

    // ---- reductions + broadcasts (overlap with stores in flight)
    #pragma unroll
    for (int o = 8; o > 0; o >>= 1) {
        a0 += __shfl_xor_sync(FULL, a0, o, 16);
        a1 += __shfl_xor_sync(FULL, a1, o, 16);
        a2 += __shfl_xor_sync(FULL, a2, o, 16);
        a3 += __shfl_xor_sync(FULL, a3, o, 16);
    }
    float xv[10];                       // xv[j] = x[10+j], lane 16+j holds it
    #pragma unroll
    for (int j = 0; j < 10; ++j)
        xv[j] = __shfl_sync(FULL, vop, 16 + j);

    // ---- compose this lane's special float4 (26 nonzero slots per row)
    float4 sv = z;
    int    w  = 0;
    if (lane == 0)       { sv = make_float4(a0, a2, 0.f, 0.f);             w = 0; }
    else if (lane == 1)  { sv = make_float4(a1, a3, 0.f, 0.f);             w = 40; }
    else if (lane < 10)  { sv = make_float4(0.f, xv[6], xv[7], xv[0]);     w = (lane - 2) * 40 + 6; }   // d 24..27
    else if (lane < 18)  { sv = make_float4(xv[1], xv[2], xv[3], xv[4]);   w = (lane - 10) * 40 + 7; }  // d 28..31
    else if (lane < 26)  { sv = make_float4(xv[5], xv[8], xv[9], 0.f);     w = (lane - 18) * 40 + 8; }  // d 32..35

    __syncwarp();                       // order zero-flood before overwrites
    if (lane < 26)
        __stcs(reinterpret_cast<float4*>(out) + row * ROW_OUT4 + w, sv);
}

extern "C" void kernel_launch(void* const* d_in, const int* in_sizes, int n_in,
                              void* d_out, int out_size)
{
    const float* x = (const float*)d_in[0];   // x_bd [B,S,512]
    float* out = (float*)d_out;               // [B,S,8,160]

    int n_rows = in_sizes[0] / BD_DIM;        // B*S = 32768
    int grid   = n_rows / 16;                 // 2048 blocks, warp-per-row

    bd2ge_reg<<<grid, THREADS>>>(x, out);
}